// round 17
// baseline (speedup 1.0000x reference)
#include <cuda_runtime.h>
#include <cuda_bf16.h>
#include <math.h>
#include <stdint.h>

// ---------------------------------------------------------------------------
// Problem dims
// ---------------------------------------------------------------------------
#define B_BATCH 16
#define T_SEQ   2048
#define D_DIM   1024
#define M_TOTAL (B_BATCH * T_SEQ)   // 32768
#define N_DIM   D_DIM
#define K_DIM   D_DIM
#define NUM_MASK 1433               // int(2048 * 0.7)

// GEMM tiling: CTA 128x256, 8 warps (2M x 4N), warp tile 64x64, TKC=32
#define TM 128
#define TN 256
#define TKC 32                      // 32 elements per K chunk (64B bf16 rows)
#define NCHUNK (K_DIM / TKC)        // 32
#define NBLK   (N_DIM / TN)         // 4
#define NTILES ((M_TOTAL / TM) * NBLK)   // 1024
#define NCTAS  148

// Stage: A_HI 8K + A_LO 8K + B_HI 16K + B_LO 16K = 48KB
#define ST_A_HI 0
#define ST_A_LO 8192
#define ST_B_HI 16384
#define ST_B_LO 32768
#define STAGE_BYTES 49152
// Raw fp32 A buffers: 128 rows x 144B (128B data + 16B pad vs bank conflicts)
#define RAW_BYTES 18432
#define SM_RAW0  (2 * STAGE_BYTES)            // 98304
#define SM_RAW1  (SM_RAW0 + RAW_BYTES)        // 116736
#define SM_PART  (SM_RAW1 + RAW_BYTES)        // 135168
#define SM_CLAIM (SM_PART + 2048)             // 137216
#define SMEM_BYTES (SM_CLAIM + 16)            // 137232

// ---------------------------------------------------------------------------
// Scratch (W only — X is consumed fp32 directly, converted in-kernel)
// ---------------------------------------------------------------------------
__device__ __align__(16) __nv_bfloat16 g_Whi[(size_t)N_DIM * K_DIM];
__device__ __align__(16) __nv_bfloat16 g_Wlo[(size_t)N_DIM * K_DIM];
__device__ float g_scores_part[NBLK][M_TOTAL];
__device__ unsigned int g_tile_counter;

// ---------------------------------------------------------------------------
// Helpers
// ---------------------------------------------------------------------------
__device__ __forceinline__ uint32_t smem_u32(const void* p) {
    uint32_t a;
    asm("{ .reg .u64 t; cvta.to.shared.u64 t, %1; cvt.u32.u64 %0, t; }"
        : "=r"(a) : "l"(p));
    return a;
}

// 64B-row swizzle (verified in round 7): unit c XOR (row>>1)&3.
__device__ __forceinline__ uint32_t swz64(int row, int c) {
    return (uint32_t)(row * 64 + ((c ^ ((row >> 1) & 3)) << 4));
}

__device__ __forceinline__ void cp_async16(uint32_t dst, const void* src) {
    asm volatile("cp.async.cg.shared.global [%0], [%1], 16;"
                 :: "r"(dst), "l"(src) : "memory");
}
__device__ __forceinline__ void cp_commit() {
    asm volatile("cp.async.commit_group;" ::: "memory");
}

__device__ __forceinline__ void ldsm4(uint32_t* r, uint32_t addr) {
    asm volatile("ldmatrix.sync.aligned.m8n8.x4.shared.b16 {%0,%1,%2,%3}, [%4];"
                 : "=r"(r[0]), "=r"(r[1]), "=r"(r[2]), "=r"(r[3]) : "r"(addr));
}

__device__ __forceinline__ void mma16816(float* c, const uint32_t* a,
                                         uint32_t b0, uint32_t b1) {
    asm volatile("mma.sync.aligned.m16n8k16.row.col.f32.bf16.bf16.f32 "
                 "{%0,%1,%2,%3}, {%4,%5,%6,%7}, {%8,%9}, {%0,%1,%2,%3};"
                 : "+f"(c[0]), "+f"(c[1]), "+f"(c[2]), "+f"(c[3])
                 : "r"(a[0]), "r"(a[1]), "r"(a[2]), "r"(a[3]), "r"(b0), "r"(b1));
}

__device__ __forceinline__ uint32_t f2key(float f) {
    uint32_t b = __float_as_uint(f);
    return b ^ ((b & 0x80000000u) ? 0xFFFFFFFFu : 0x80000000u);
}
__device__ __forceinline__ float key2f(uint32_t k) {
    return __uint_as_float(k ^ ((k & 0x80000000u) ? 0x80000000u : 0xFFFFFFFFu));
}

// fp32 pair -> packed bf16x2 hi/lo (identical math to old split kernels)
__device__ __forceinline__ void split2(float f0, float f1,
                                       uint32_t& hi, uint32_t& lo) {
    __nv_bfloat16 h0 = __float2bfloat16(f0);
    __nv_bfloat16 h1 = __float2bfloat16(f1);
    __nv_bfloat16 l0 = __float2bfloat16(f0 - __bfloat162float(h0));
    __nv_bfloat16 l1 = __float2bfloat16(f1 - __bfloat162float(h1));
    __nv_bfloat162 hv = __halves2bfloat162(h0, h1);
    __nv_bfloat162 lv = __halves2bfloat162(l0, l1);
    hi = *reinterpret_cast<uint32_t*>(&hv);
    lo = *reinterpret_cast<uint32_t*>(&lv);
}

// ---------------------------------------------------------------------------
// Kernel 0: split W fp32 -> bf16 hi/lo (4MB). Also resets tile counter.
// ---------------------------------------------------------------------------
__global__ __launch_bounds__(256)
void split_w_kernel(const float* __restrict__ src)
{
    if (blockIdx.x == 0 && threadIdx.x == 0) g_tile_counter = 0u;
    int i = blockIdx.x * 256 + threadIdx.x;
    float4 v = ((const float4*)src)[i];
    uint32_t h0, l0, h1, l1;
    split2(v.x, v.y, h0, l0);
    split2(v.z, v.w, h1, l1);
    ((uint32_t*)g_Whi)[2 * i]     = h0;
    ((uint32_t*)g_Whi)[2 * i + 1] = h1;
    ((uint32_t*)g_Wlo)[2 * i]     = l0;
    ((uint32_t*)g_Wlo)[2 * i + 1] = l1;
}

// ---------------------------------------------------------------------------
// Kernel 1: persistent split-bf16 score GEMM with pipelined fused X split.
// Per chunk c: wait_group 0 -> BAR -> issue {B(c+1), rawA(c+2)} ->
//   convert(c+1) [raw fp32 -> bf16 hi/lo, overlaps MMA in-flight] ->
//   MMA(c) -> BAR.
// Conversion of c+1 has no dependency on MMA(c) -> scheduler interleaves it
// into the tensor pipe's idle slots. split_x kernel (256MB DRAM) eliminated.
// Chunk & term order unchanged -> scores bitwise identical.
// ---------------------------------------------------------------------------
__global__ __launch_bounds__(256, 1)
void gemm_score_mma(const float* __restrict__ xg,
                    const float* __restrict__ b1, const float* __restrict__ w2)
{
    extern __shared__ char smem[];
    const uint32_t sb = smem_u32(smem);
    const int tid = threadIdx.x;
    const int wid = tid >> 5;
    const int lane = tid & 31;
    const int warp_m = wid >> 2;    // 0..1
    const int warp_n = wid & 3;     // 0..3

    int* claimp = (int*)(smem + SM_CLAIM);
    float* part = (float*)(smem + SM_PART);

#define CLAIM(dst)                                                            \
    do {                                                                      \
        if (tid == 0) *claimp = (int)atomicAdd(&g_tile_counter, 1u);          \
        __syncthreads();                                                      \
        (dst) = *claimp;                                                      \
        __syncthreads();                                                      \
    } while (0)

    int cur, nxt;
    CLAIM(cur);
    if (cur >= NTILES) return;
    CLAIM(nxt);

    int cur_m0 = (cur >> 2) * TM, cur_n0 = (cur & 3) * TN;
    int nxt_m0 = 0, nxt_n0 = 0;
    if (nxt < NTILES) { nxt_m0 = (nxt >> 2) * TM; nxt_n0 = (nxt & 3) * TN; }

    float acc[4][8][4];
#pragma unroll
    for (int a = 0; a < 4; ++a)
#pragma unroll
        for (int b = 0; b < 8; ++b)
#pragma unroll
            for (int cc = 0; cc < 4; ++cc) acc[a][b][cc] = 0.0f;

    // cp.async mappings
    //   rawA: 1024 units (128 rows x 8 x 16B); 4 per thread
    //   B hi/lo: 1024 units each (256 rows x 4 x 16B); 4 per thread each
#define ISSUE_RAWA(p, c, mb)                                                  \
    do {                                                                      \
        const uint32_t rb_ = sb + SM_RAW0 + (p) * RAW_BYTES;                  \
        _Pragma("unroll")                                                     \
        for (int i_ = 0; i_ < 4; ++i_) {                                      \
            const int g_ = tid + i_ * 256;                                    \
            const int row_ = g_ >> 3, u_ = g_ & 7;                            \
            cp_async16(rb_ + row_ * 144 + u_ * 16,                            \
                       xg + (size_t)((mb) + row_) * K_DIM + (c) * TKC + u_ * 4); \
        }                                                                     \
    } while (0)

#define ISSUE_B(p, c, nb)                                                     \
    do {                                                                      \
        const uint32_t st_ = sb + (p) * STAGE_BYTES;                          \
        const size_t ko_ = (size_t)(c) * TKC;                                 \
        _Pragma("unroll")                                                     \
        for (int i_ = 0; i_ < 4; ++i_) {                                      \
            const int g_ = tid + i_ * 256;                                    \
            const int row_ = g_ >> 2, u_ = g_ & 3;                            \
            const uint32_t sw_ = swz64(row_, u_);                             \
            const size_t go_ = (size_t)((nb) + row_) * K_DIM + ko_ + u_ * 8;  \
            cp_async16(st_ + ST_B_HI + sw_, g_Whi + go_);                     \
            cp_async16(st_ + ST_B_LO + sw_, g_Wlo + go_);                     \
        }                                                                     \
    } while (0)

    // Conversion: thread -> row tid>>1, half tid&1 (16 floats = 64B raw)
    const int cr = tid >> 1;
    const int chh = tid & 1;

#define CONVERT(p)                                                            \
    do {                                                                      \
        const uint32_t rb_ = sb + SM_RAW0 + (p) * RAW_BYTES + cr * 144 + chh * 64; \
        const uint32_t stA_ = sb + (p) * STAGE_BYTES;                         \
        _Pragma("unroll")                                                     \
        for (int j_ = 0; j_ < 2; ++j_) {                                      \
            float4 f0_, f1_;                                                  \
            asm volatile("ld.shared.v4.f32 {%0,%1,%2,%3}, [%4];"              \
                : "=f"(f0_.x), "=f"(f0_.y), "=f"(f0_.z), "=f"(f0_.w)          \
                : "r"(rb_ + j_ * 32));                                        \
            asm volatile("ld.shared.v4.f32 {%0,%1,%2,%3}, [%4];"              \
                : "=f"(f1_.x), "=f"(f1_.y), "=f"(f1_.z), "=f"(f1_.w)          \
                : "r"(rb_ + j_ * 32 + 16));                                   \
            uint32_t h0_, l0_, h1_, l1_, h2_, l2_, h3_, l3_;                  \
            split2(f0_.x, f0_.y, h0_, l0_);                                   \
            split2(f0_.z, f0_.w, h1_, l1_);                                   \
            split2(f1_.x, f1_.y, h2_, l2_);                                   \
            split2(f1_.z, f1_.w, h3_, l3_);                                   \
            const uint32_t sw_ = swz64(cr, 2 * chh + j_);                     \
            asm volatile("st.shared.v4.b32 [%0], {%1,%2,%3,%4};"              \
                :: "r"(stA_ + ST_A_HI + sw_), "r"(h0_), "r"(h1_), "r"(h2_), "r"(h3_) \
                : "memory");                                                  \
            asm volatile("st.shared.v4.b32 [%0], {%1,%2,%3,%4};"              \
                :: "r"(stA_ + ST_A_LO + sw_), "r"(l0_), "r"(l1_), "r"(l2_), "r"(l3_) \
                : "memory");                                                  \
        }                                                                     \
    } while (0)

    // ldmatrix address components
    const int a_row = warp_m * 64 + (lane & 15);
    const int a_chsel = (lane >> 4);
    const int b_row = warp_n * 64 + ((lane >> 4) << 3) + (lane & 7);
    const int b_chsel = ((lane >> 3) & 1);

    // Prologue: one group {rawA(0), B(0), rawA(1)}; wait all; convert(0).
    ISSUE_RAWA(0, 0, cur_m0);
    ISSUE_B(0, 0, cur_n0);
    ISSUE_RAWA(1, 1, cur_m0);
    cp_commit();
    asm volatile("cp.async.wait_group 0;" ::: "memory");
    __syncthreads();
    CONVERT(0);

    while (true) {
#pragma unroll 1
        for (int c = 0; c < NCHUNK; ++c) {
            asm volatile("cp.async.wait_group 0;" ::: "memory");
            __syncthreads();   // BAR1: publish group; order prev convert/MMA

            // issue {B(c+1), rawA(c+2)} (linearized across tile boundary)
            {
                const int ib = c + 1;
                if (ib < NCHUNK)           ISSUE_B(ib & 1, ib, cur_n0);
                else if (nxt < NTILES)     ISSUE_B(ib & 1, ib - NCHUNK, nxt_n0);
                const int ia = c + 2;
                if (ia < NCHUNK)           ISSUE_RAWA(ia & 1, ia, cur_m0);
                else if (nxt < NTILES)     ISSUE_RAWA(ia & 1, ia - NCHUNK, nxt_m0);
                cp_commit();
            }

            // convert chunk c+1 (overlaps with MMA below; no dependency)
            {
                const int ic = c + 1;
                if (ic < NCHUNK || nxt < NTILES) CONVERT(ic & 1);
            }

            // MMA on stage c&1 (term-major; per-acc order hh -> hl -> lh)
            const uint32_t st = sb + (c & 1) * STAGE_BYTES;
#pragma unroll
            for (int kk = 0; kk < 2; ++kk) {
                const int ch = kk * 2;
                uint32_t ah[4][4], bh[4][4];
#pragma unroll
                for (int mt = 0; mt < 4; ++mt)
                    ldsm4(ah[mt], st + ST_A_HI + swz64(a_row + mt * 16, a_chsel + ch));
#pragma unroll
                for (int nt2 = 0; nt2 < 4; ++nt2)
                    ldsm4(bh[nt2], st + ST_B_HI + swz64(b_row + nt2 * 16, b_chsel + ch));
#pragma unroll
                for (int mt = 0; mt < 4; ++mt)
#pragma unroll
                    for (int nt = 0; nt < 8; ++nt) {
                        const int nt2 = nt >> 1, hh = (nt & 1) * 2;
                        mma16816(acc[mt][nt], ah[mt], bh[nt2][hh], bh[nt2][hh + 1]);
                    }
                uint32_t bl[4][4];
#pragma unroll
                for (int nt2 = 0; nt2 < 4; ++nt2)
                    ldsm4(bl[nt2], st + ST_B_LO + swz64(b_row + nt2 * 16, b_chsel + ch));
#pragma unroll
                for (int mt = 0; mt < 4; ++mt)
#pragma unroll
                    for (int nt = 0; nt < 8; ++nt) {
                        const int nt2 = nt >> 1, hh = (nt & 1) * 2;
                        mma16816(acc[mt][nt], ah[mt], bl[nt2][hh], bl[nt2][hh + 1]);
                    }
                uint32_t al[4][4];
#pragma unroll
                for (int mt = 0; mt < 4; ++mt)
                    ldsm4(al[mt], st + ST_A_LO + swz64(a_row + mt * 16, a_chsel + ch));
#pragma unroll
                for (int mt = 0; mt < 4; ++mt)
#pragma unroll
                    for (int nt = 0; nt < 8; ++nt) {
                        const int nt2 = nt >> 1, hh = (nt & 1) * 2;
                        mma16816(acc[mt][nt], al[mt], bh[nt2][hh], bh[nt2][hh + 1]);
                    }
            }
            __syncthreads();   // BAR2: convert(c+1)/MMA(c) done before next writes
        }

        // ---------------- Epilogue for tile `cur` ----------------
        {
            const int g = lane >> 2, q = lane & 3;
            float rsum[8];
#pragma unroll
            for (int i = 0; i < 8; ++i) rsum[i] = 0.0f;
#pragma unroll
            for (int nt = 0; nt < 8; ++nt) {
                const int col0 = cur_n0 + warp_n * 64 + nt * 8 + q * 2;
                const float w0 = w2[col0],     bb0 = b1[col0];
                const float w1 = w2[col0 + 1], bb1 = b1[col0 + 1];
#pragma unroll
                for (int mt = 0; mt < 4; ++mt) {
                    rsum[mt * 2 + 0] += w0 * tanhf(acc[mt][nt][0] + bb0);
                    rsum[mt * 2 + 0] += w1 * tanhf(acc[mt][nt][1] + bb1);
                    rsum[mt * 2 + 1] += w0 * tanhf(acc[mt][nt][2] + bb0);
                    rsum[mt * 2 + 1] += w1 * tanhf(acc[mt][nt][3] + bb1);
                }
            }
#pragma unroll
            for (int i = 0; i < 8; ++i) {
                rsum[i] += __shfl_xor_sync(0xffffffffu, rsum[i], 1);
                rsum[i] += __shfl_xor_sync(0xffffffffu, rsum[i], 2);
            }
            if (q == 0) {
#pragma unroll
                for (int mt = 0; mt < 4; ++mt) {
                    part[warp_n * 128 + warp_m * 64 + mt * 16 + g]     = rsum[mt * 2 + 0];
                    part[warp_n * 128 + warp_m * 64 + mt * 16 + 8 + g] = rsum[mt * 2 + 1];
                }
            }
            __syncthreads();
            if (tid < TM) {
                const float ssum = part[tid] + part[128 + tid] +
                                   part[256 + tid] + part[384 + tid];
                g_scores_part[cur & 3][cur_m0 + tid] = ssum;
            }
        }

        if (nxt >= NTILES) break;
        cur = nxt; cur_m0 = nxt_m0; cur_n0 = nxt_n0;
        CLAIM(nxt);
        if (nxt < NTILES) { nxt_m0 = (nxt >> 2) * TM; nxt_n0 = (nxt & 3) * TN; }

#pragma unroll
        for (int a = 0; a < 4; ++a)
#pragma unroll
            for (int b = 0; b < 8; ++b)
#pragma unroll
                for (int cc = 0; cc < 4; ++cc) acc[a][b][cc] = 0.0f;
    }
}

// ---------------------------------------------------------------------------
// Kernel 2: per-batch softmax + radix-select threshold + mask -> weights.
// (identical to the 520.3us round)
// ---------------------------------------------------------------------------
__global__ __launch_bounds__(1024)
void softmax_mask_kernel(float* __restrict__ wout)
{
    __shared__ float sv[T_SEQ];
    __shared__ unsigned int keys[T_SEQ];
    __shared__ float red[1024];
    __shared__ int hist[256];
    __shared__ int wsum[8];
    __shared__ int sel_bin, sel_excl;

    const int b = blockIdx.x;
    const int tid = threadIdx.x;
    const size_t base = (size_t)b * T_SEQ;

    for (int t = tid; t < T_SEQ; t += 1024) {
        float s = 0.0f;
#pragma unroll
        for (int p = 0; p < NBLK; ++p) s += g_scores_part[p][base + t];
        sv[t] = s;
        keys[t] = f2key(s);
    }
    __syncthreads();

    unsigned int pref = 0;
    int k = NUM_MASK;
#pragma unroll
    for (int pass = 0; pass < 4; ++pass) {
        const int shift = 24 - 8 * pass;
        const unsigned int pmask = (pass == 0) ? 0u : (0xFFFFFFFFu << (shift + 8));
        if (tid < 256) hist[tid] = 0;
        __syncthreads();
        for (int t = tid; t < T_SEQ; t += 1024) {
            const unsigned int key = keys[t];
            if ((key & pmask) == pref)
                atomicAdd(&hist[(key >> shift) & 0xFF], 1);
        }
        __syncthreads();
        int incl = 0, hv = 0;
        if (tid < 256) {
            const int l = tid & 31;
            hv = hist[tid];
            incl = hv;
#pragma unroll
            for (int off = 1; off < 32; off <<= 1) {
                int n = __shfl_up_sync(0xffffffffu, incl, off);
                if (l >= off) incl += n;
            }
            if (l == 31) wsum[tid >> 5] = incl;
        }
        __syncthreads();
        if (tid < 256) {
            const int w = tid >> 5;
            int add = 0;
#pragma unroll
            for (int j = 0; j < 7; ++j)
                if (j < w) add += wsum[j];
            incl += add;
            const int excl = incl - hv;
            if (excl <= k && k < incl) { sel_bin = tid; sel_excl = excl; }
        }
        __syncthreads();
        pref |= ((unsigned int)sel_bin) << shift;
        k -= sel_excl;
        __syncthreads();
    }
    const float thr = key2f(pref);

    float m = -INFINITY;
    for (int t = tid; t < T_SEQ; t += 1024) m = fmaxf(m, sv[t]);
    red[tid] = m;
    __syncthreads();
    for (int s = 512; s > 0; s >>= 1) {
        if (tid < s) red[tid] = fmaxf(red[tid], red[tid + s]);
        __syncthreads();
    }
    const float mx = red[0];
    __syncthreads();

    float sum = 0.0f;
    for (int t = tid; t < T_SEQ; t += 1024) sum += expf(sv[t] - mx);
    red[tid] = sum;
    __syncthreads();
    for (int s = 512; s > 0; s >>= 1) {
        if (tid < s) red[tid] += red[tid + s];
        __syncthreads();
    }
    const float inv = 1.0f / red[0];

    for (int t = tid; t < T_SEQ; t += 1024) {
        const float sc = sv[t];
        const float w = expf(sc - mx) * inv;
        wout[base + t] = (sc >= thr) ? w : 0.0f;
    }
}

// ---------------------------------------------------------------------------
// Kernel 3: masked_output = x * weights. Mask-aware (skip x reads of zeroed
// rows). (identical to the 520.3us round)
// ---------------------------------------------------------------------------
__global__ __launch_bounds__(256)
void scale_kernel(const float* __restrict__ x,
                  const float* __restrict__ mw,
                  float* __restrict__ out)
{
    const size_t row0 = (size_t)blockIdx.x * 8;
    const int t = threadIdx.x;
    const float4* xi = (const float4*)(x + row0 * D_DIM);
    float4* o = (float4*)(out + row0 * D_DIM);

    float w[8];
#pragma unroll
    for (int r = 0; r < 8; ++r) w[r] = __ldg(mw + row0 + r);

    float4 v[8];
#pragma unroll
    for (int r = 0; r < 8; ++r) {
        if (w[r] != 0.0f) v[r] = __ldg(xi + (size_t)r * 256 + t);
        else              v[r] = make_float4(0.0f, 0.0f, 0.0f, 0.0f);
    }
#pragma unroll
    for (int r = 0; r < 8; ++r) {
        float4 ov = make_float4(v[r].x * w[r], v[r].y * w[r],
                                v[r].z * w[r], v[r].w * w[r]);
        __stcs(o + (size_t)r * 256 + t, ov);
    }
}

// ---------------------------------------------------------------------------
extern "C" void kernel_launch(void* const* d_in, const int* in_sizes, int n_in,
                              void* d_out, int out_size)
{
    const float* x  = (const float*)d_in[0];
    const float* W1 = (const float*)d_in[1];
    const float* b1 = (const float*)d_in[2];
    const float* w2 = (const float*)d_in[3];
    // b2 shifts all scores uniformly -> softmax/rank invariant; unused.
    (void)in_sizes; (void)n_in; (void)out_size;

    float* out_masked  = (float*)d_out;
    float* out_weights = out_masked + (size_t)M_TOTAL * D_DIM;

    cudaFuncSetAttribute(gemm_score_mma,
                         cudaFuncAttributeMaxDynamicSharedMemorySize, SMEM_BYTES);

    split_w_kernel<<<(N_DIM * K_DIM) / 4 / 256, 256>>>(W1);   // also resets counter

    gemm_score_mma<<<NCTAS, 256, SMEM_BYTES>>>(x, b1, w2);

    softmax_mask_kernel<<<B_BATCH, 1024>>>(out_weights);
    scale_kernel<<<M_TOTAL / 8, 256>>>(x, out_weights, out_masked);
}